// round 15
// baseline (speedup 1.0000x reference)
#include <cuda_runtime.h>

#define NS 512   // samples
#define DE 512   // embedding dim
#define NC 5     // classes
#define KSPLIT 8
#define KCHUNK (DE / KSPLIT)   // 64

// ---------------- device scratch (no allocation allowed) ----------------
__device__ __align__(16) float g_part[KSPLIT][NS * NS];  // raw partial dots (8 MB)
__device__ __align__(16) float g_diag[KSPLIT][NS];       // compact Gram-diagonal partials
__device__ float g_sum;                    // global loss sum
__device__ int   g_nz;                     // global nonzero count
__device__ int   g_done;                   // completed loss blocks

// ---------------- f32x2 packed helpers (sm_103a) ----------------
__device__ __forceinline__ unsigned long long dupf(float a) {
    unsigned long long d;
    asm("mov.b64 %0, {%1, %1};" : "=l"(d) : "f"(a));
    return d;
}
__device__ __forceinline__ unsigned long long fma2(unsigned long long a,
                                                   unsigned long long b,
                                                   unsigned long long c) {
    unsigned long long d;
    asm("fma.rn.f32x2 %0, %1, %2, %3;" : "=l"(d) : "l"(a), "l"(b), "l"(c));
    return d;
}
__device__ __forceinline__ float2 unpk(unsigned long long v) {
    float2 r;
    asm("mov.b64 {%0, %1}, %2;" : "=f"(r.x), "=f"(r.y) : "l"(v));
    return r;
}

// ---------------- kernel 1: partial-K raw dot GEMM (exact R10, validated) ----
__global__ void __launch_bounds__(128) gemm_kernel(const float* __restrict__ x) {
    __shared__ __align__(16) float As[32][68];  // [k][row], 64 rows + pad
    __shared__ __align__(16) float Bs[32][36];  // [k][row], 32 rows + pad

    int t = threadIdx.x;           // 0..127
    int bj = blockIdx.x;           // col tile (32 wide)
    int bi = blockIdx.y;           // row tile (64 tall)
    int z = blockIdx.z;            // K chunk

    if (bj == 0 && bi == 0 && z == 0 && t == 0) {
        g_sum = 0.f; g_nz = 0; g_done = 0;   // re-zeroed on every graph replay
    }

    int tx = t & 7, ty = t >> 3;       // 8x16 micro grid, 4x4 each
    int arow = t >> 1, asel = t & 1;   // A loads: 2 thr/row, 4 f4 each
    int brow = t >> 2, bsel = t & 3;   // B loads: 4 thr/row, 2 f4 each

    unsigned long long acc[4][2];
    #pragma unroll
    for (int r = 0; r < 4; r++) { acc[r][0] = 0ull; acc[r][1] = 0ull; }

    int kbeg = z * KCHUNK;
    #pragma unroll
    for (int k0 = kbeg; k0 < kbeg + KCHUNK; k0 += 32) {
        float4 a[4], b[2];
        const float4* gA = (const float4*)(x + (size_t)(bi * 64 + arow) * DE + k0);
        #pragma unroll
        for (int q = 0; q < 4; q++) a[q] = gA[asel + 2 * q];
        const float4* gB = (const float4*)(x + (size_t)(bj * 32 + brow) * DE + k0);
        #pragma unroll
        for (int q = 0; q < 2; q++) b[q] = gB[bsel + 4 * q];
        __syncthreads();
        #pragma unroll
        for (int q = 0; q < 4; q++) {
            int c = 4 * (asel + 2 * q);
            As[c + 0][arow] = a[q].x; As[c + 1][arow] = a[q].y;
            As[c + 2][arow] = a[q].z; As[c + 3][arow] = a[q].w;
        }
        #pragma unroll
        for (int q = 0; q < 2; q++) {
            int c = 4 * (bsel + 4 * q);
            Bs[c + 0][brow] = b[q].x; Bs[c + 1][brow] = b[q].y;
            Bs[c + 2][brow] = b[q].z; Bs[c + 3][brow] = b[q].w;
        }
        __syncthreads();
        #pragma unroll
        for (int kk = 0; kk < 32; kk++) {
            float4 av = *(const float4*)&As[kk][4 * ty];
            ulonglong2 bv = *(const ulonglong2*)&Bs[kk][4 * tx];
            unsigned long long a0 = dupf(av.x), a1 = dupf(av.y);
            unsigned long long a2 = dupf(av.z), a3 = dupf(av.w);
            acc[0][0] = fma2(a0, bv.x, acc[0][0]); acc[0][1] = fma2(a0, bv.y, acc[0][1]);
            acc[1][0] = fma2(a1, bv.x, acc[1][0]); acc[1][1] = fma2(a1, bv.y, acc[1][1]);
            acc[2][0] = fma2(a2, bv.x, acc[2][0]); acc[2][1] = fma2(a2, bv.y, acc[2][1]);
            acc[3][0] = fma2(a3, bv.x, acc[3][0]); acc[3][1] = fma2(a3, bv.y, acc[3][1]);
        }
    }

    bool diag = ((bj >> 1) == bi) && (ty == (((bj & 1) << 3) + tx));

    float* dst = g_part[z];
    #pragma unroll
    for (int r = 0; r < 4; r++) {
        float2 p0 = unpk(acc[r][0]);
        float2 p1 = unpk(acc[r][1]);
        float4 o;
        o.x = p0.x; o.y = p0.y; o.z = p1.x; o.w = p1.y;
        *(float4*)&dst[(size_t)(bi * 64 + 4 * ty + r) * NS + bj * 32 + 4 * tx] = o;
        if (diag) {
            float dval = (r == 0) ? o.x : (r == 1) ? o.y : (r == 2) ? o.z : o.w;
            g_diag[z][bi * 64 + 4 * ty + r] = dval;
        }
    }
}

// ---------------- kernel 2: per-anchor loss + fused finalize ----------------
// one block per anchor i, 256 threads. Setup (R10): thread t owns cols 2t,2t+1.
// Inner: 2-D register tile — thread (pg, jc) holds 8 thresholds in regs and
// scans a ~7-float4 j strip; each LDS serves 8 positives. Partials combined
// via spread-address smem atomicAdd into sacc[], then folded.
__global__ void __launch_bounds__(256) loss_kernel(const float* __restrict__ dist_raw,
                                                   const int* __restrict__ target,
                                                   float* __restrict__ out) {
    __shared__ __align__(16) float bvals[NS];  // cos[i,j]+margin, or -1e30
    __shared__ __align__(16) float rns[NS];    // 1/max(||x_j||, 1e-8)
    __shared__ float crow[NS];
    __shared__ float cps[NS];
    __shared__ int klist[NS];
    __shared__ float sacc[NS];                 // per-positive accumulators
    __shared__ float cls_pos[NC];
    __shared__ int kcnt, scount;
    __shared__ float red_s[8];
    __shared__ int red_n[8];

    int i = blockIdx.x;
    int t = threadIdx.x;
    int c0 = 2 * t;
    int wid = t >> 5, lid = t & 31;

    if (t == 0) {
        kcnt = 0; scount = 0;
        float c = 0.f;
        cls_pos[0] = 0.f;
        #pragma unroll
        for (int q = 0; q < NC - 1; q++) {
            c += log1pf(expf(dist_raw[q]));  // softplus cumsum
            cls_pos[q + 1] = c;
        }
    }

    // reconstruct 1/norm from compact diagonal partials (coalesced float2)
    float rj0, rj1;
    {
        float sx = 0.f, sy = 0.f;
        #pragma unroll
        for (int z = 0; z < KSPLIT; z++) {
            float2 p = *(const float2*)&g_diag[z][c0];
            sx += p.x; sy += p.y;
        }
        rj0 = 1.0f / fmaxf(sqrtf(sx), 1e-8f);
        rj1 = 1.0f / fmaxf(sqrtf(sy), 1e-8f);
        rns[c0] = rj0;
        rns[c0 + 1] = rj1;
    }
    __syncthreads();

    // cos row i: sum 8 K-partials, scale by rn_i*rn_j
    float ri = rns[i];
    {
        size_t off = (size_t)i * NS + c0;
        float sx = 0.f, sy = 0.f;
        #pragma unroll
        for (int z = 0; z < KSPLIT; z++) {
            float2 p = *(const float2*)&g_part[z][off];
            sx += p.x; sy += p.y;
        }
        crow[c0] = sx * ri * rj0;
        crow[c0 + 1] = sy * ri * rj1;
        int2 tg = *(const int2*)&target[c0];
        cps[c0] = cls_pos[tg.x];
        cps[c0 + 1] = cls_pos[tg.y];
    }
    __syncthreads();

    float cpi = cps[i];
    int myc = 0;
    #pragma unroll
    for (int q = 0; q < 2; q++) {
        int j = c0 + q;
        float m = fabsf(cpi - cps[j]);
        bool same = (m == 0.0f);  // class_pos strictly increasing -> equality iff same class
        bvals[j] = same ? -1e30f : (crow[j] + m);
        if (same) {
            myc++;
            if (j != i) klist[atomicAdd(&kcnt, 1)] = j;
        }
    }
    atomicAdd(&scount, myc);
    sacc[c0] = 0.f; sacc[c0 + 1] = 0.f;
    __syncthreads();

    int nk = kcnt;
    int negc = NS - scount;
    float inv = 1.0f / (float)(negc > 1 ? negc : 1);

    // 2-D decomposition: PG positive-groups of 8, JC j-chunks
    int PG = (nk + 7) >> 3;
    if (PG < 1) PG = 1;
    int JC = 256 / PG;
    int pg = t % PG;
    int jc = t / PG;
    const float4* bv4 = (const float4*)bvals;

    if (jc < JC && nk > 0) {
        float c[8];
        #pragma unroll
        for (int q = 0; q < 8; q++) {
            int p = pg * 8 + q;
            c[q] = (p < nk) ? crow[klist[p]] : 3e38f;   // pad -> relu 0
        }
        int nf4 = (NS / 4 + JC - 1) / JC;
        int f0 = jc * nf4;
        int f1 = f0 + nf4;
        if (f1 > NS / 4) f1 = NS / 4;
        float a[8];
        #pragma unroll
        for (int q = 0; q < 8; q++) a[q] = 0.f;
        for (int f = f0; f < f1; f++) {
            float4 bv = bv4[f];
            #pragma unroll
            for (int q = 0; q < 8; q++) {
                a[q] += fmaxf(bv.x - c[q], 0.f) + fmaxf(bv.y - c[q], 0.f)
                      + fmaxf(bv.z - c[q], 0.f) + fmaxf(bv.w - c[q], 0.f);
            }
        }
        #pragma unroll
        for (int q = 0; q < 8; q++) {
            int p = pg * 8 + q;
            if (p < nk && a[q] != 0.f) atomicAdd(&sacc[p], a[q]);
        }
    }
    __syncthreads();

    // fold per-positive accumulators
    float lsum = 0.f;
    int lnz = 0;
    for (int r = t; r < nk; r += 256) {
        float acc = sacc[r];
        lsum += acc * inv;
        lnz += (acc != 0.f) ? 1 : 0;
    }

    // block reduce (8 warps)
    for (int o = 16; o > 0; o >>= 1) {
        lsum += __shfl_down_sync(0xffffffffu, lsum, o);
        lnz += __shfl_down_sync(0xffffffffu, lnz, o);
    }
    if (lid == 0) { red_s[wid] = lsum; red_n[wid] = lnz; }
    __syncthreads();

    // fused finalize: last block to finish computes the output
    if (t == 0) {
        float bs = 0.f; int bn = 0;
        #pragma unroll
        for (int w = 0; w < 8; w++) { bs += red_s[w]; bn += red_n[w]; }
        atomicAdd(&g_sum, bs);
        atomicAdd(&g_nz, bn);
        __threadfence();
        if (atomicAdd(&g_done, 1) == NS - 1) {
            __threadfence();
            float S = *(volatile float*)&g_sum;
            int N = *(volatile int*)&g_nz;
            out[0] = S / (float)(N > 1 ? N : 1);
        }
    }
}

extern "C" void kernel_launch(void* const* d_in, const int* in_sizes, int n_in,
                              void* d_out, int out_size) {
    const float* pred = (const float*)d_in[0];   // [512, 512] f32
    const float* draw = (const float*)d_in[1];   // [4] f32
    const int* target = (const int*)d_in[2];     // [512] i32
    float* out = (float*)d_out;

    gemm_kernel<<<dim3(16, 8, KSPLIT), 128>>>(pred);
    loss_kernel<<<NS, 256>>>(draw, target, out);
}

// round 16
// speedup vs baseline: 1.1649x; 1.1649x over previous
#include <cuda_runtime.h>

#define NS 512   // samples
#define DE 512   // embedding dim
#define NC 5     // classes
#define KSPLIT 8
#define KCHUNK (DE / KSPLIT)   // 64

// ---------------- device scratch (no allocation allowed) ----------------
__device__ __align__(16) float g_part[KSPLIT][NS * NS];  // raw partial dots (8 MB)
__device__ __align__(16) float g_diag[KSPLIT][NS];       // compact Gram-diagonal partials
__device__ float g_sum;                    // global loss sum
__device__ int   g_nz;                     // global nonzero count
__device__ int   g_done;                   // completed loss blocks

// ---------------- f32x2 packed helpers (sm_103a) ----------------
__device__ __forceinline__ unsigned long long dupf(float a) {
    unsigned long long d;
    asm("mov.b64 %0, {%1, %1};" : "=l"(d) : "f"(a));
    return d;
}
__device__ __forceinline__ unsigned long long fma2(unsigned long long a,
                                                   unsigned long long b,
                                                   unsigned long long c) {
    unsigned long long d;
    asm("fma.rn.f32x2 %0, %1, %2, %3;" : "=l"(d) : "l"(a), "l"(b), "l"(c));
    return d;
}
__device__ __forceinline__ float2 unpk(unsigned long long v) {
    float2 r;
    asm("mov.b64 {%0, %1}, %2;" : "=f"(r.x), "=f"(r.y) : "l"(v));
    return r;
}

// ---------------- kernel 1: partial-K raw dot GEMM (exact R10, validated) ----
__global__ void __launch_bounds__(128) gemm_kernel(const float* __restrict__ x) {
    __shared__ __align__(16) float As[32][68];  // [k][row], 64 rows + pad
    __shared__ __align__(16) float Bs[32][36];  // [k][row], 32 rows + pad

    int t = threadIdx.x;           // 0..127
    int bj = blockIdx.x;           // col tile (32 wide)
    int bi = blockIdx.y;           // row tile (64 tall)
    int z = blockIdx.z;            // K chunk

    if (bj == 0 && bi == 0 && z == 0 && t == 0) {
        g_sum = 0.f; g_nz = 0; g_done = 0;   // re-zeroed on every graph replay
    }

    int tx = t & 7, ty = t >> 3;       // 8x16 micro grid, 4x4 each
    int arow = t >> 1, asel = t & 1;   // A loads: 2 thr/row, 4 f4 each
    int brow = t >> 2, bsel = t & 3;   // B loads: 4 thr/row, 2 f4 each

    unsigned long long acc[4][2];
    #pragma unroll
    for (int r = 0; r < 4; r++) { acc[r][0] = 0ull; acc[r][1] = 0ull; }

    int kbeg = z * KCHUNK;
    #pragma unroll
    for (int k0 = kbeg; k0 < kbeg + KCHUNK; k0 += 32) {
        float4 a[4], b[2];
        const float4* gA = (const float4*)(x + (size_t)(bi * 64 + arow) * DE + k0);
        #pragma unroll
        for (int q = 0; q < 4; q++) a[q] = gA[asel + 2 * q];
        const float4* gB = (const float4*)(x + (size_t)(bj * 32 + brow) * DE + k0);
        #pragma unroll
        for (int q = 0; q < 2; q++) b[q] = gB[bsel + 4 * q];
        __syncthreads();
        #pragma unroll
        for (int q = 0; q < 4; q++) {
            int c = 4 * (asel + 2 * q);
            As[c + 0][arow] = a[q].x; As[c + 1][arow] = a[q].y;
            As[c + 2][arow] = a[q].z; As[c + 3][arow] = a[q].w;
        }
        #pragma unroll
        for (int q = 0; q < 2; q++) {
            int c = 4 * (bsel + 4 * q);
            Bs[c + 0][brow] = b[q].x; Bs[c + 1][brow] = b[q].y;
            Bs[c + 2][brow] = b[q].z; Bs[c + 3][brow] = b[q].w;
        }
        __syncthreads();
        #pragma unroll
        for (int kk = 0; kk < 32; kk++) {
            float4 av = *(const float4*)&As[kk][4 * ty];
            ulonglong2 bv = *(const ulonglong2*)&Bs[kk][4 * tx];
            unsigned long long a0 = dupf(av.x), a1 = dupf(av.y);
            unsigned long long a2 = dupf(av.z), a3 = dupf(av.w);
            acc[0][0] = fma2(a0, bv.x, acc[0][0]); acc[0][1] = fma2(a0, bv.y, acc[0][1]);
            acc[1][0] = fma2(a1, bv.x, acc[1][0]); acc[1][1] = fma2(a1, bv.y, acc[1][1]);
            acc[2][0] = fma2(a2, bv.x, acc[2][0]); acc[2][1] = fma2(a2, bv.y, acc[2][1]);
            acc[3][0] = fma2(a3, bv.x, acc[3][0]); acc[3][1] = fma2(a3, bv.y, acc[3][1]);
        }
    }

    bool diag = ((bj >> 1) == bi) && (ty == (((bj & 1) << 3) + tx));

    float* dst = g_part[z];
    #pragma unroll
    for (int r = 0; r < 4; r++) {
        float2 p0 = unpk(acc[r][0]);
        float2 p1 = unpk(acc[r][1]);
        float4 o;
        o.x = p0.x; o.y = p0.y; o.z = p1.x; o.w = p1.y;
        *(float4*)&dst[(size_t)(bi * 64 + 4 * ty + r) * NS + bj * 32 + 4 * tx] = o;
        if (diag) {
            float dval = (r == 0) ? o.x : (r == 1) ? o.y : (r == 2) ? o.z : o.w;
            g_diag[z][bi * 64 + 4 * ty + r] = dval;
        }
    }
}

// ---------------- kernel 2: per-anchor loss + fused finalize ----------------
// one block per anchor i, 256 threads (exact R10 structure). Thread t owns
// columns 2t, 2t+1. Inner loop: 2 threads per positive, INTERLEAVED float4
// access (even lane f=2jj, odd f=2jj+1) -> warp touches 2 consecutive float4
// = 8 distinct banks, conflict-free broadcast (fixes R10's 2-way conflict).
__global__ void __launch_bounds__(256) loss_kernel(const float* __restrict__ dist_raw,
                                                   const int* __restrict__ target,
                                                   float* __restrict__ out) {
    __shared__ __align__(16) float bvals[NS];  // cos[i,j]+margin, or -1e30
    __shared__ __align__(16) float rns[NS];    // 1/max(||x_j||, 1e-8)
    __shared__ float crow[NS];
    __shared__ float cps[NS];
    __shared__ int klist[NS];
    __shared__ float cls_pos[NC];
    __shared__ int kcnt, scount;
    __shared__ float red_s[8];
    __shared__ int red_n[8];

    int i = blockIdx.x;
    int t = threadIdx.x;
    int c0 = 2 * t;

    if (t == 0) {
        kcnt = 0; scount = 0;
        float c = 0.f;
        cls_pos[0] = 0.f;
        #pragma unroll
        for (int q = 0; q < NC - 1; q++) {
            c += log1pf(expf(dist_raw[q]));  // softplus cumsum
            cls_pos[q + 1] = c;
        }
    }

    // reconstruct 1/norm from compact diagonal partials (coalesced float2)
    float rj0, rj1;
    {
        float sx = 0.f, sy = 0.f;
        #pragma unroll
        for (int z = 0; z < KSPLIT; z++) {
            float2 p = *(const float2*)&g_diag[z][c0];
            sx += p.x; sy += p.y;
        }
        rj0 = 1.0f / fmaxf(sqrtf(sx), 1e-8f);
        rj1 = 1.0f / fmaxf(sqrtf(sy), 1e-8f);
        rns[c0] = rj0;
        rns[c0 + 1] = rj1;
    }
    __syncthreads();

    // cos row i: sum 8 K-partials, scale by rn_i*rn_j
    float ri = rns[i];
    {
        size_t off = (size_t)i * NS + c0;
        float sx = 0.f, sy = 0.f;
        #pragma unroll
        for (int z = 0; z < KSPLIT; z++) {
            float2 p = *(const float2*)&g_part[z][off];
            sx += p.x; sy += p.y;
        }
        crow[c0] = sx * ri * rj0;
        crow[c0 + 1] = sy * ri * rj1;
        int2 tg = *(const int2*)&target[c0];
        cps[c0] = cls_pos[tg.x];
        cps[c0 + 1] = cls_pos[tg.y];
    }
    __syncthreads();

    float cpi = cps[i];
    int myc = 0;
    #pragma unroll
    for (int q = 0; q < 2; q++) {
        int j = c0 + q;
        float m = fabsf(cpi - cps[j]);
        bool same = (m == 0.0f);  // class_pos strictly increasing -> equality iff same class
        bvals[j] = same ? -1e30f : (crow[j] + m);
        if (same) {
            myc++;
            if (j != i) klist[atomicAdd(&kcnt, 1)] = j;
        }
    }
    atomicAdd(&scount, myc);
    __syncthreads();

    int nk = kcnt;
    int negc = NS - scount;
    float inv = 1.0f / (float)(negc > 1 ? negc : 1);

    float lsum = 0.f;
    int lnz = 0;
    const float4* bv4 = (const float4*)bvals;
    // 2 threads per positive, interleaved j-chunks (conflict-free):
    // even lane sums f = 0,2,4,..., odd lane f = 1,3,5,...
    int iters = (2 * nk + 255) >> 8;   // uniform trip count for shfl safety
    for (int it = 0; it < iters; it++) {
        int p2 = t + (it << 8);
        bool active = p2 < 2 * nk;
        int pid = active ? (p2 >> 1) : 0;
        int half = p2 & 1;
        float cik = crow[klist[pid]];
        float acc0 = 0.f, acc1 = 0.f;
        #pragma unroll 8
        for (int jj = 0; jj < 64; jj++) {
            float4 bv = bv4[2 * jj + half];
            acc0 += fmaxf(bv.x - cik, 0.f) + fmaxf(bv.y - cik, 0.f);
            acc1 += fmaxf(bv.z - cik, 0.f) + fmaxf(bv.w - cik, 0.f);
        }
        float acc = acc0 + acc1;
        acc += __shfl_xor_sync(0xffffffffu, acc, 1);   // combine halves
        if (active && half == 0) {
            lsum += acc * inv;
            lnz += (acc != 0.f) ? 1 : 0;
        }
    }

    // block reduce (8 warps)
    for (int o = 16; o > 0; o >>= 1) {
        lsum += __shfl_down_sync(0xffffffffu, lsum, o);
        lnz += __shfl_down_sync(0xffffffffu, lnz, o);
    }
    int wid = t >> 5, lid = t & 31;
    if (lid == 0) { red_s[wid] = lsum; red_n[wid] = lnz; }
    __syncthreads();

    // fused finalize: last block to finish computes the output
    if (t == 0) {
        float bs = 0.f; int bn = 0;
        #pragma unroll
        for (int w = 0; w < 8; w++) { bs += red_s[w]; bn += red_n[w]; }
        atomicAdd(&g_sum, bs);
        atomicAdd(&g_nz, bn);
        __threadfence();
        if (atomicAdd(&g_done, 1) == NS - 1) {
            __threadfence();
            float S = *(volatile float*)&g_sum;
            int N = *(volatile int*)&g_nz;
            out[0] = S / (float)(N > 1 ? N : 1);
        }
    }
}

extern "C" void kernel_launch(void* const* d_in, const int* in_sizes, int n_in,
                              void* d_out, int out_size) {
    const float* pred = (const float*)d_in[0];   // [512, 512] f32
    const float* draw = (const float*)d_in[1];   // [4] f32
    const int* target = (const int*)d_in[2];     // [512] i32
    float* out = (float*)d_out;

    gemm_kernel<<<dim3(16, 8, KSPLIT), 128>>>(pred);
    loss_kernel<<<NS, 256>>>(draw, target, out);
}

// round 17
// speedup vs baseline: 1.2424x; 1.0665x over previous
#include <cuda_runtime.h>

#define NS 512   // samples
#define DE 512   // embedding dim
#define NC 5     // classes
#define KSPLIT 8
#define KCHUNK (DE / KSPLIT)   // 64

// ---------------- device scratch (no allocation allowed) ----------------
__device__ __align__(16) float g_part[KSPLIT][NS * NS];  // raw partial dots (8 MB)
__device__ __align__(16) float g_diag[KSPLIT][NS];       // compact Gram-diagonal partials
__device__ float g_sum;                    // global loss sum
__device__ int   g_nz;                     // global nonzero count
__device__ int   g_done;                   // completed loss blocks

// ---------------- f32x2 packed helpers (sm_103a) ----------------
__device__ __forceinline__ unsigned long long dupf(float a) {
    unsigned long long d;
    asm("mov.b64 %0, {%1, %1};" : "=l"(d) : "f"(a));
    return d;
}
__device__ __forceinline__ unsigned long long fma2(unsigned long long a,
                                                   unsigned long long b,
                                                   unsigned long long c) {
    unsigned long long d;
    asm("fma.rn.f32x2 %0, %1, %2, %3;" : "=l"(d) : "l"(a), "l"(b), "l"(c));
    return d;
}
__device__ __forceinline__ float2 unpk(unsigned long long v) {
    float2 r;
    asm("mov.b64 {%0, %1}, %2;" : "=f"(r.x), "=f"(r.y) : "l"(v));
    return r;
}

// ---------------- kernel 1: partial-K raw dot GEMM (exact R10, validated) ----
__global__ void __launch_bounds__(128) gemm_kernel(const float* __restrict__ x) {
    __shared__ __align__(16) float As[32][68];  // [k][row], 64 rows + pad
    __shared__ __align__(16) float Bs[32][36];  // [k][row], 32 rows + pad

    int t = threadIdx.x;           // 0..127
    int bj = blockIdx.x;           // col tile (32 wide)
    int bi = blockIdx.y;           // row tile (64 tall)
    int z = blockIdx.z;            // K chunk

    if (bj == 0 && bi == 0 && z == 0 && t == 0) {
        g_sum = 0.f; g_nz = 0; g_done = 0;   // re-zeroed on every graph replay
    }

    int tx = t & 7, ty = t >> 3;       // 8x16 micro grid, 4x4 each
    int arow = t >> 1, asel = t & 1;   // A loads: 2 thr/row, 4 f4 each
    int brow = t >> 2, bsel = t & 3;   // B loads: 4 thr/row, 2 f4 each

    unsigned long long acc[4][2];
    #pragma unroll
    for (int r = 0; r < 4; r++) { acc[r][0] = 0ull; acc[r][1] = 0ull; }

    int kbeg = z * KCHUNK;
    #pragma unroll
    for (int k0 = kbeg; k0 < kbeg + KCHUNK; k0 += 32) {
        float4 a[4], b[2];
        const float4* gA = (const float4*)(x + (size_t)(bi * 64 + arow) * DE + k0);
        #pragma unroll
        for (int q = 0; q < 4; q++) a[q] = gA[asel + 2 * q];
        const float4* gB = (const float4*)(x + (size_t)(bj * 32 + brow) * DE + k0);
        #pragma unroll
        for (int q = 0; q < 2; q++) b[q] = gB[bsel + 4 * q];
        __syncthreads();
        #pragma unroll
        for (int q = 0; q < 4; q++) {
            int c = 4 * (asel + 2 * q);
            As[c + 0][arow] = a[q].x; As[c + 1][arow] = a[q].y;
            As[c + 2][arow] = a[q].z; As[c + 3][arow] = a[q].w;
        }
        #pragma unroll
        for (int q = 0; q < 2; q++) {
            int c = 4 * (bsel + 4 * q);
            Bs[c + 0][brow] = b[q].x; Bs[c + 1][brow] = b[q].y;
            Bs[c + 2][brow] = b[q].z; Bs[c + 3][brow] = b[q].w;
        }
        __syncthreads();
        #pragma unroll
        for (int kk = 0; kk < 32; kk++) {
            float4 av = *(const float4*)&As[kk][4 * ty];
            ulonglong2 bv = *(const ulonglong2*)&Bs[kk][4 * tx];
            unsigned long long a0 = dupf(av.x), a1 = dupf(av.y);
            unsigned long long a2 = dupf(av.z), a3 = dupf(av.w);
            acc[0][0] = fma2(a0, bv.x, acc[0][0]); acc[0][1] = fma2(a0, bv.y, acc[0][1]);
            acc[1][0] = fma2(a1, bv.x, acc[1][0]); acc[1][1] = fma2(a1, bv.y, acc[1][1]);
            acc[2][0] = fma2(a2, bv.x, acc[2][0]); acc[2][1] = fma2(a2, bv.y, acc[2][1]);
            acc[3][0] = fma2(a3, bv.x, acc[3][0]); acc[3][1] = fma2(a3, bv.y, acc[3][1]);
        }
    }

    bool diag = ((bj >> 1) == bi) && (ty == (((bj & 1) << 3) + tx));

    float* dst = g_part[z];
    #pragma unroll
    for (int r = 0; r < 4; r++) {
        float2 p0 = unpk(acc[r][0]);
        float2 p1 = unpk(acc[r][1]);
        float4 o;
        o.x = p0.x; o.y = p0.y; o.z = p1.x; o.w = p1.y;
        *(float4*)&dst[(size_t)(bi * 64 + 4 * ty + r) * NS + bj * 32 + 4 * tx] = o;
        if (diag) {
            float dval = (r == 0) ? o.x : (r == 1) ? o.y : (r == 2) ? o.z : o.w;
            g_diag[z][bi * 64 + 4 * ty + r] = dval;
        }
    }
}

// ---------------- kernel 2: per-anchor loss + fused finalize ----------------
// one block per anchor i, 256 threads (R16 structure). Thread t owns columns
// 2t, 2t+1. Inner loop uses the identity
//   sum_j relu(b_j - c) = sum_j max(b_j, c) - 512*c     (over ALL j; masked
// entries b=-1e30 give max=c and cancel exactly), reducing 3 instrs/element
// to 2 (FMNMX on alu pipe + FADD on fma pipe).
__global__ void __launch_bounds__(256) loss_kernel(const float* __restrict__ dist_raw,
                                                   const int* __restrict__ target,
                                                   float* __restrict__ out) {
    __shared__ __align__(16) float bvals[NS];  // cos[i,j]+margin, or -1e30
    __shared__ __align__(16) float rns[NS];    // 1/max(||x_j||, 1e-8)
    __shared__ float crow[NS];
    __shared__ float cps[NS];
    __shared__ int klist[NS];
    __shared__ float cls_pos[NC];
    __shared__ int kcnt, scount;
    __shared__ float red_s[8];
    __shared__ int red_n[8];

    int i = blockIdx.x;
    int t = threadIdx.x;
    int c0 = 2 * t;

    if (t == 0) {
        kcnt = 0; scount = 0;
        float c = 0.f;
        cls_pos[0] = 0.f;
        #pragma unroll
        for (int q = 0; q < NC - 1; q++) {
            c += log1pf(expf(dist_raw[q]));  // softplus cumsum
            cls_pos[q + 1] = c;
        }
    }

    // reconstruct 1/norm from compact diagonal partials (coalesced float2)
    float rj0, rj1;
    {
        float sx = 0.f, sy = 0.f;
        #pragma unroll
        for (int z = 0; z < KSPLIT; z++) {
            float2 p = *(const float2*)&g_diag[z][c0];
            sx += p.x; sy += p.y;
        }
        rj0 = 1.0f / fmaxf(sqrtf(sx), 1e-8f);
        rj1 = 1.0f / fmaxf(sqrtf(sy), 1e-8f);
        rns[c0] = rj0;
        rns[c0 + 1] = rj1;
    }
    __syncthreads();

    // cos row i: sum 8 K-partials, scale by rn_i*rn_j
    float ri = rns[i];
    {
        size_t off = (size_t)i * NS + c0;
        float sx = 0.f, sy = 0.f;
        #pragma unroll
        for (int z = 0; z < KSPLIT; z++) {
            float2 p = *(const float2*)&g_part[z][off];
            sx += p.x; sy += p.y;
        }
        crow[c0] = sx * ri * rj0;
        crow[c0 + 1] = sy * ri * rj1;
        int2 tg = *(const int2*)&target[c0];
        cps[c0] = cls_pos[tg.x];
        cps[c0 + 1] = cls_pos[tg.y];
    }
    __syncthreads();

    float cpi = cps[i];
    int myc = 0;
    #pragma unroll
    for (int q = 0; q < 2; q++) {
        int j = c0 + q;
        float m = fabsf(cpi - cps[j]);
        bool same = (m == 0.0f);  // class_pos strictly increasing -> equality iff same class
        bvals[j] = same ? -1e30f : (crow[j] + m);
        if (same) {
            myc++;
            if (j != i) klist[atomicAdd(&kcnt, 1)] = j;
        }
    }
    atomicAdd(&scount, myc);
    __syncthreads();

    int nk = kcnt;
    int negc = NS - scount;
    float inv = 1.0f / (float)(negc > 1 ? negc : 1);

    float lsum = 0.f;
    int lnz = 0;
    const float4* bv4 = (const float4*)bvals;
    // 2 threads per positive, interleaved j-chunks (conflict-free):
    // even lane sums f = 0,2,4,..., odd lane f = 1,3,5,...
    int iters = (2 * nk + 255) >> 8;   // uniform trip count for shfl safety
    for (int it = 0; it < iters; it++) {
        int p2 = t + (it << 8);
        bool active = p2 < 2 * nk;
        int pid = active ? (p2 >> 1) : 0;
        int half = p2 & 1;
        float cik = crow[klist[pid]];
        float acc0 = 0.f, acc1 = 0.f;
        #pragma unroll 8
        for (int jj = 0; jj < 64; jj++) {
            float4 bv = bv4[2 * jj + half];
            acc0 += fmaxf(bv.x, cik) + fmaxf(bv.y, cik);
            acc1 += fmaxf(bv.z, cik) + fmaxf(bv.w, cik);
        }
        float acc = acc0 + acc1;
        acc += __shfl_xor_sync(0xffffffffu, acc, 1);   // combine halves
        if (active && half == 0) {
            float val = acc - 512.0f * cik;   // = sum relu(b - cik)
            lsum += val * inv;
            lnz += (val != 0.f) ? 1 : 0;
        }
    }

    // block reduce (8 warps)
    for (int o = 16; o > 0; o >>= 1) {
        lsum += __shfl_down_sync(0xffffffffu, lsum, o);
        lnz += __shfl_down_sync(0xffffffffu, lnz, o);
    }
    int wid = t >> 5, lid = t & 31;
    if (lid == 0) { red_s[wid] = lsum; red_n[wid] = lnz; }
    __syncthreads();

    // fused finalize: last block to finish computes the output
    if (t == 0) {
        float bs = 0.f; int bn = 0;
        #pragma unroll
        for (int w = 0; w < 8; w++) { bs += red_s[w]; bn += red_n[w]; }
        atomicAdd(&g_sum, bs);
        atomicAdd(&g_nz, bn);
        __threadfence();
        if (atomicAdd(&g_done, 1) == NS - 1) {
            __threadfence();
            float S = *(volatile float*)&g_sum;
            int N = *(volatile int*)&g_nz;
            out[0] = S / (float)(N > 1 ? N : 1);
        }
    }
}

extern "C" void kernel_launch(void* const* d_in, const int* in_sizes, int n_in,
                              void* d_out, int out_size) {
    const float* pred = (const float*)d_in[0];   // [512, 512] f32
    const float* draw = (const float*)d_in[1];   // [4] f32
    const int* target = (const int*)d_in[2];     // [512] i32
    float* out = (float*)d_out;

    gemm_kernel<<<dim3(16, 8, KSPLIT), 128>>>(pred);
    loss_kernel<<<NS, 256>>>(draw, target, out);
}